// round 17
// baseline (speedup 1.0000x reference)
#include <cuda_runtime.h>
#include <stdint.h>

// Problem constants
#define NBINS      32
#define NCH        64            // B*C = 8*8
#define HW         65536         // 256*256 pixels per channel
#define NSUB       256           // fine histogram sub-bins over [0,1)
#define CTAS_PER_CH 8
#define NCTA      (NCH * CTAS_PER_CH)       // 512
#define F4_PER_CTA ((HW / 4) / CTAS_PER_CH) // 2048 float4 per CTA
#define PAD        32            // +-4 sigma = +-32 sub-bins (sigma = 8 sub)
#define WIN        (2 * PAD)     // 64
#define NSTEP      (WIN / 32)    // 2 strided warp steps

#define AMPL   0.3989472f        // ER/RATIO = 1/2.5066
#define INV31  (1.0f / 31.0f)    // bin spacing (linspace(0,1,32))
#define K512   512.0f            // 1/(2*sigma^2), sigma = 1/32
#define DELTA  (1.0f / 256.0f)   // sub-bin width
#define STEP32 (32.0f * DELTA)   // lane stride in x (= 4 sigma)

static __device__ __forceinline__ uint32_t smem_u32(const void* p)
{
    uint32_t a;
    asm("{ .reg .u64 t; cvta.to.shared.u64 t, %1; cvt.u32.u64 %0, t; }"
        : "=r"(a) : "l"(p));
    return a;
}

// ---------------------------------------------------------------------------
// Single launch. One cluster (8 CTAs) per channel; one CTA per slab
// (8192 pixels). All 512 CTAs are co-resident (33.5 KB smem -> 6 CTAs/SM,
// 6*148 >= 512), so cluster barriers are cheap and deadlock-free.
//
// Phase 0: zero s_out + histogram table; cluster barrier #1 (doubles as the
//          CTA barrier AND guarantees rank0's s_out is zero before any peer
//          DSMEM red can arrive).
// Phase 1: bank-decorated shared-atomic histogram hw[bin*32 | lane]: all 32
//          lanes hit distinct banks -> single-phase ATOMS, no replay
//          (R15's proven 8.8us configuration).
// Phase 2: thread t sums bin t's 32 lane slots (staggered, conflict-free)
//          -> +-PAD zero-padded float array.
// Phase 3: warp-per-bin Gaussian window (4 bins/warp, 2 steps, lattice
//          recurrence, 2 expf per bin-lane); lane0 fire-and-forget
//          red.shared::cluster.add.f32 into cluster-rank-0's s_out.
// Phase 4: cluster barrier #2 (arrive=release / wait=acquire orders the
//          reds); rank0 CTA writes out[ch*32..] with plain STG.
//          -> NO output zeroing, NO global atomics, NO second launch.
// ---------------------------------------------------------------------------
__global__ __launch_bounds__(256, 6) __cluster_dims__(CTAS_PER_CH, 1, 1)
void fused_kernel(const float* __restrict__ x, float* __restrict__ out)
{
    __shared__ unsigned int hw[NSUB * 32];     // 32 KB lane-column histogram
    __shared__ float        hf[NSUB + WIN];    // 1.25 KB padded floats
    __shared__ float        s_out[NBINS];      // cluster-reduced result (rank0)

    const int tid  = threadIdx.x;
    const int warp = tid >> 5;
    const int lane = tid & 31;

    uint32_t rank;
    asm("mov.u32 %0, %%cluster_ctarank;" : "=r"(rank));

    // ---- Phase 0: zero smem, cluster barrier #1 ---------------------------
    if (tid < NBINS) s_out[tid] = 0.0f;
    #pragma unroll
    for (int i = tid; i < NSUB * 32; i += 256) hw[i] = 0u;

    asm volatile("barrier.cluster.arrive.aligned;" ::: "memory");
    asm volatile("barrier.cluster.wait.aligned;"   ::: "memory");

    // ---- Phase 1: bank-conflict-free shared-atomic histogram --------------
    const float4* __restrict__ p =
        reinterpret_cast<const float4*>(x) + (size_t)blockIdx.x * F4_PER_CTA;

    #pragma unroll
    for (int i = tid; i < F4_PER_CTA; i += 256) {
        float4 v = p[i];
        int i0 = ((int)(v.x * (float)NSUB) << 5) | lane;
        int i1 = ((int)(v.y * (float)NSUB) << 5) | lane;
        int i2 = ((int)(v.z * (float)NSUB) << 5) | lane;
        int i3 = ((int)(v.w * (float)NSUB) << 5) | lane;
        atomicAdd(&hw[i0], 1u);   // all lanes -> distinct banks: 1 phase
        atomicAdd(&hw[i1], 1u);
        atomicAdd(&hw[i2], 1u);
        atomicAdd(&hw[i3], 1u);
    }
    __syncthreads();

    // ---- Phase 2: column-sum 32 lane slots per bin (staggered) ------------
    {
        unsigned int s = 0u;
        const int base = tid << 5;
        #pragma unroll
        for (int k = 0; k < 32; k++)
            s += hw[base + ((k + lane) & 31)];
        hf[PAD + tid] = (float)s;
        if (tid < PAD) {
            hf[tid] = 0.0f;
            hf[PAD + NSUB + tid] = 0.0f;
        }
    }
    __syncthreads();

    // ---- Phase 3: warp-per-bin convolution, DSMEM red to rank0 ------------
    const float gS = __expf(-2.0f * K512 * STEP32 * STEP32);

    // rank0's s_out base address in the cluster aperture
    uint32_t rem_base;
    {
        uint32_t loc = smem_u32(&s_out[0]);
        asm("mapa.shared::cluster.u32 %0, %1, %2;"
            : "=r"(rem_base) : "r"(loc), "r"(0));
    }

    #pragma unroll
    for (int b = 0; b < 4; b++) {
        const int j = warp + 8 * b;                 // bin 0..31
        const float cj = (float)j * INV31;
        const int icenter = (int)(cj * (float)NSUB);
        const float d0 = ((float)(icenter - PAD + lane) + 0.5f) * DELTA - cj;

        float w = __expf(-d0 * d0 * K512);
        float r = __expf(-K512 * STEP32 * (2.0f * d0 + STEP32));

        int idx = icenter + lane;                   // = PAD + m0 + lane
        float acc = 0.0f;
        #pragma unroll
        for (int i = 0; i < NSTEP; i++) {
            acc = fmaf(hf[idx], w, acc);
            w *= r;
            r *= gS;
            idx += 32;
        }

        // full-warp reduce
        #pragma unroll
        for (int off = 16; off > 0; off >>= 1)
            acc += __shfl_down_sync(0xFFFFFFFFu, acc, off);

        if (lane == 0) {
            float val = acc * AMPL;
            asm volatile("red.shared::cluster.add.f32 [%0], %1;"
                         :: "r"(rem_base + (uint32_t)(j * 4)), "f"(val)
                         : "memory");
        }
    }

    // ---- Phase 4: cluster barrier #2, rank0 writes the channel ------------
    asm volatile("barrier.cluster.arrive.aligned;" ::: "memory");
    asm volatile("barrier.cluster.wait.aligned;"   ::: "memory");

    if (rank == 0 && tid < NBINS) {
        const int ch = blockIdx.x >> 3;
        out[ch * NBINS + tid] = s_out[tid];
    }
}

// ---------------------------------------------------------------------------
extern "C" void kernel_launch(void* const* d_in, const int* in_sizes, int n_in,
                              void* d_out, int out_size)
{
    const float* x = (const float*)d_in[0];   // [8,8,256,256] fp32
    float* out = (float*)d_out;               // [8,256,1,1] = 2048 fp32

    fused_kernel<<<NCTA, 256>>>(x, out);
}